// round 16
// baseline (speedup 1.0000x reference)
#include <cuda_runtime.h>
#include <cstdint>

// ============================================================================
// SpecialFC: out[b] = x[b] @ W[b]^T + bias[b]
//   x: [8, 8192, 512] f32,  W: [8, 512, 512] f32,  bias: [8, 512] f32
//
// Base-target-legal tensor path (harness PTX target is compute_103, which
// rejects all tcgen05/"a" features): tf32 mma.sync.m16n8k8 + cp.async
// 4-stage pipeline. CTA tile 128x128, warp tile 64x32, K chunks of 32.
// ============================================================================

namespace sfc {

constexpr int BATCH = 8;
constexpr int NSEQ  = 8192;
constexpr int CIN   = 512;
constexpr int COUT  = 512;

constexpr int BM = 128;
constexpr int BN = 128;
constexpr int BK = 32;
constexpr int CHUNKS  = CIN / BK;          // 16
constexpr int THREADS = 256;               // 8 warps

constexpr int MTILES = NSEQ / BM;          // 64
constexpr int NTILES = COUT / BN;          // 4
constexpr int GRID   = BATCH * MTILES * NTILES; // 2048

// Padded smem stride: 32+4 floats -> (4*row + col) % 32 distinct per quad,
// conflict-free lds.32 fragment loads.
constexpr int LDA      = BK + 4;           // 36 floats = 144 B per row
constexpr int STAGE_AF = BM * LDA;         // A floats per stage (4608)
constexpr int STAGE_BF = BN * LDA;         // B floats per stage (4608)
constexpr int STAGE_F  = STAGE_AF + STAGE_BF;       // 9216 floats
constexpr int STAGE_BYTES = STAGE_F * 4;            // 36864 B
constexpr int NSTAGE   = 4;
constexpr unsigned SMEM_TOTAL = NSTAGE * STAGE_BYTES; // 147456 B

__device__ __forceinline__ uint32_t smem_u32(const void* p) {
    uint32_t a;
    asm("{ .reg .u64 t; cvta.to.shared.u64 t, %1; cvt.u32.u64 %0, t; }"
        : "=r"(a) : "l"(p));
    return a;
}

__device__ __forceinline__ void cp16(uint32_t dst, const float* src) {
    asm volatile("cp.async.cg.shared.global [%0], [%1], 16;"
                 :: "r"(dst), "l"(src) : "memory");
}

__device__ __forceinline__ uint32_t tf32_of(float f) {
    uint32_t r;
    asm("cvt.rna.tf32.f32 %0, %1;" : "=r"(r) : "f"(f));
    return r;
}

__device__ __forceinline__ void mma8(float* c, const uint32_t* a, const uint32_t* b) {
    asm volatile(
        "mma.sync.aligned.m16n8k8.row.col.f32.tf32.tf32.f32 "
        "{%0,%1,%2,%3}, {%4,%5,%6,%7}, {%8,%9}, {%0,%1,%2,%3};"
        : "+f"(c[0]), "+f"(c[1]), "+f"(c[2]), "+f"(c[3])
        : "r"(a[0]), "r"(a[1]), "r"(a[2]), "r"(a[3]),
          "r"(b[0]), "r"(b[1]));
}

// Load one K-chunk: A = x[m0:m0+128, k0:k0+32], B = W[n0:n0+128, k0:k0+32],
// both into padded-stride smem via cp.async 16B granules. 256 threads.
__device__ __forceinline__ void load_chunk(
    const float* __restrict__ x, const float* __restrict__ W,
    uint32_t smem_base, int stage, int b, int m0, int n0, int k0, int tid) {

    const uint32_t sa = smem_base + stage * STAGE_BYTES;
    const uint32_t sb = sa + STAGE_AF * 4;

    const float* xs = x + ((size_t)b * NSEQ + m0) * CIN + k0;
    const float* ws = W + ((size_t)b * COUT + n0) * CIN + k0;

#pragma unroll
    for (int i = 0; i < 4; i++) {            // 1024 x 16B for A
        const int idx = tid + i * THREADS;
        const int row = idx >> 3;
        const int g   = idx & 7;
        cp16(sa + (uint32_t)(row * LDA + g * 4) * 4, xs + (size_t)row * CIN + g * 4);
    }
#pragma unroll
    for (int i = 0; i < 4; i++) {            // 1024 x 16B for B
        const int idx = tid + i * THREADS;
        const int row = idx >> 3;
        const int g   = idx & 7;
        cp16(sb + (uint32_t)(row * LDA + g * 4) * 4, ws + (size_t)row * CIN + g * 4);
    }
}

} // namespace sfc

using namespace sfc;

__global__ void __launch_bounds__(THREADS, 1)
special_fc_mma_kernel(const float* __restrict__ x,
                      const float* __restrict__ W,
                      const float* __restrict__ bias,
                      float* __restrict__ out) {
    extern __shared__ float smem[];
    const uint32_t smem_base = smem_u32(smem);
    const int tid  = threadIdx.x;
    const int warp = tid >> 5;
    const int lane = tid & 31;
    const int rg   = lane >> 2;   // groupID (0..7)
    const int tg   = lane & 3;    // thread-in-group (0..3)

    // Block decomposition: 4 consecutive CTAs share the x tile (n varies
    // fastest), 256 consecutive CTAs share W[b].
    const int b   = blockIdx.x >> 8;
    const int rem = blockIdx.x & 255;
    const int m0  = (rem >> 2) * BM;
    const int n0  = (rem & 3) * BN;

    // Warp tile: 64 (m) x 32 (n).  wm in {0,1}, wn in {0..3}.
    const int wm = warp >> 2;
    const int wn = warp & 3;

    float acc[4][4][4];           // [mt][nt][c0..c3]
#pragma unroll
    for (int mt = 0; mt < 4; mt++)
#pragma unroll
        for (int nt = 0; nt < 4; nt++)
#pragma unroll
            for (int j = 0; j < 4; j++)
                acc[mt][nt][j] = 0.0f;

    // ---- prologue: 3 chunks in flight ----
#pragma unroll
    for (int s = 0; s < NSTAGE - 1; s++) {
        load_chunk(x, W, smem_base, s, b, m0, n0, s * BK, tid);
        asm volatile("cp.async.commit_group;" ::: "memory");
    }

    // ---- main loop over K chunks ----
#pragma unroll 1
    for (int c = 0; c < CHUNKS; ++c) {
        asm volatile("cp.async.wait_group %0;" :: "n"(NSTAGE - 2) : "memory");
        __syncthreads();

        // refill the stage freed by chunk c-1 (computed last iteration)
        if (c + NSTAGE - 1 < CHUNKS) {
            load_chunk(x, W, smem_base, (c + NSTAGE - 1) & (NSTAGE - 1),
                       b, m0, n0, (c + NSTAGE - 1) * BK, tid);
        }
        asm volatile("cp.async.commit_group;" ::: "memory");

        const float* As = smem + (size_t)(c & (NSTAGE - 1)) * STAGE_F;
        const float* Bs = As + STAGE_AF;

#pragma unroll
        for (int kk = 0; kk < BK; kk += 8) {
            uint32_t afr[4][4];
#pragma unroll
            for (int mt = 0; mt < 4; mt++) {
                const float* ap = As + (wm * 64 + mt * 16 + rg) * LDA + kk + tg;
                afr[mt][0] = tf32_of(ap[0]);
                afr[mt][1] = tf32_of(ap[8 * LDA]);
                afr[mt][2] = tf32_of(ap[4]);
                afr[mt][3] = tf32_of(ap[8 * LDA + 4]);
            }
            uint32_t bfr[4][2];
#pragma unroll
            for (int nt = 0; nt < 4; nt++) {
                const float* bp = Bs + (wn * 32 + nt * 8 + rg) * LDA + kk + tg;
                bfr[nt][0] = tf32_of(bp[0]);
                bfr[nt][1] = tf32_of(bp[4]);
            }
#pragma unroll
            for (int mt = 0; mt < 4; mt++)
#pragma unroll
                for (int nt = 0; nt < 4; nt++)
                    mma8(acc[mt][nt], afr[mt], bfr[nt]);
        }
        __syncthreads();
    }

    // ---- epilogue: bias add + float2 stores ----
    float2 bv[4];
#pragma unroll
    for (int nt = 0; nt < 4; nt++) {
        const int col = n0 + wn * 32 + nt * 8 + 2 * tg;
        bv[nt] = *reinterpret_cast<const float2*>(bias + b * COUT + col);
    }

#pragma unroll
    for (int mt = 0; mt < 4; mt++) {
        const int rbase = m0 + wm * 64 + mt * 16 + rg;
#pragma unroll
        for (int half = 0; half < 2; half++) {
            float* po = out + ((size_t)b * NSEQ + rbase + half * 8) * COUT;
#pragma unroll
            for (int nt = 0; nt < 4; nt++) {
                const int col = n0 + wn * 32 + nt * 8 + 2 * tg;
                float2 v;
                v.x = acc[mt][nt][half * 2 + 0] + bv[nt].x;
                v.y = acc[mt][nt][half * 2 + 1] + bv[nt].y;
                *reinterpret_cast<float2*>(po + col) = v;
            }
        }
    }
}

extern "C" void kernel_launch(void* const* d_in, const int* in_sizes, int n_in,
                              void* d_out, int out_size) {
    const float* x    = (const float*)d_in[0];
    const float* W    = (const float*)d_in[1];
    const float* bias = (const float*)d_in[2];
    float* out        = (float*)d_out;

    cudaFuncSetAttribute(special_fc_mma_kernel,
                         cudaFuncAttributeMaxDynamicSharedMemorySize, SMEM_TOTAL);
    special_fc_mma_kernel<<<GRID, THREADS, SMEM_TOTAL>>>(x, W, bias, out);
}

// round 17
// speedup vs baseline: 1.0003x; 1.0003x over previous
#include <cuda_runtime.h>
#include <cstdint>

// ============================================================================
// SpecialFC: out[b] = x[b] @ W[b]^T + bias[b]
//   x: [8, 8192, 512] f32,  W: [8, 512, 512] f32,  bias: [8, 512] f32
//
// Base-target-legal tensor path (harness PTX target is compute_103, which
// rejects all tcgen05/"a" features): tf32 mma.sync.m16n8k8 + cp.async
// 4-stage pipeline. CTA tile 128x128, warp tile 64x32, K chunks of 32.
// ============================================================================

namespace sfc {

constexpr int BATCH = 8;
constexpr int NSEQ  = 8192;
constexpr int CIN   = 512;
constexpr int COUT  = 512;

constexpr int BM = 128;
constexpr int BN = 128;
constexpr int BK = 32;
constexpr int CHUNKS  = CIN / BK;          // 16
constexpr int THREADS = 256;               // 8 warps

constexpr int MTILES = NSEQ / BM;          // 64
constexpr int NTILES = COUT / BN;          // 4
constexpr int GRID   = BATCH * MTILES * NTILES; // 2048

// Padded smem stride: 32+4 floats -> (4*row + col) % 32 distinct per quad,
// conflict-free lds.32 fragment loads.
constexpr int LDA      = BK + 4;           // 36 floats = 144 B per row
constexpr int STAGE_AF = BM * LDA;         // A floats per stage (4608)
constexpr int STAGE_BF = BN * LDA;         // B floats per stage (4608)
constexpr int STAGE_F  = STAGE_AF + STAGE_BF;       // 9216 floats
constexpr int STAGE_BYTES = STAGE_F * 4;            // 36864 B
constexpr int NSTAGE   = 4;
constexpr unsigned SMEM_TOTAL = NSTAGE * STAGE_BYTES; // 147456 B

__device__ __forceinline__ uint32_t smem_u32(const void* p) {
    uint32_t a;
    asm("{ .reg .u64 t; cvta.to.shared.u64 t, %1; cvt.u32.u64 %0, t; }"
        : "=r"(a) : "l"(p));
    return a;
}

__device__ __forceinline__ void cp16(uint32_t dst, const float* src) {
    asm volatile("cp.async.cg.shared.global [%0], [%1], 16;"
                 :: "r"(dst), "l"(src) : "memory");
}

__device__ __forceinline__ uint32_t tf32_of(float f) {
    uint32_t r;
    asm("cvt.rna.tf32.f32 %0, %1;" : "=r"(r) : "f"(f));
    return r;
}

__device__ __forceinline__ void mma8(float* c, const uint32_t* a, const uint32_t* b) {
    asm volatile(
        "mma.sync.aligned.m16n8k8.row.col.f32.tf32.tf32.f32 "
        "{%0,%1,%2,%3}, {%4,%5,%6,%7}, {%8,%9}, {%0,%1,%2,%3};"
        : "+f"(c[0]), "+f"(c[1]), "+f"(c[2]), "+f"(c[3])
        : "r"(a[0]), "r"(a[1]), "r"(a[2]), "r"(a[3]),
          "r"(b[0]), "r"(b[1]));
}

// Load one K-chunk: A = x[m0:m0+128, k0:k0+32], B = W[n0:n0+128, k0:k0+32],
// both into padded-stride smem via cp.async 16B granules. 256 threads.
__device__ __forceinline__ void load_chunk(
    const float* __restrict__ x, const float* __restrict__ W,
    uint32_t smem_base, int stage, int b, int m0, int n0, int k0, int tid) {

    const uint32_t sa = smem_base + stage * STAGE_BYTES;
    const uint32_t sb = sa + STAGE_AF * 4;

    const float* xs = x + ((size_t)b * NSEQ + m0) * CIN + k0;
    const float* ws = W + ((size_t)b * COUT + n0) * CIN + k0;

#pragma unroll
    for (int i = 0; i < 4; i++) {            // 1024 x 16B for A
        const int idx = tid + i * THREADS;
        const int row = idx >> 3;
        const int g   = idx & 7;
        cp16(sa + (uint32_t)(row * LDA + g * 4) * 4, xs + (size_t)row * CIN + g * 4);
    }
#pragma unroll
    for (int i = 0; i < 4; i++) {            // 1024 x 16B for B
        const int idx = tid + i * THREADS;
        const int row = idx >> 3;
        const int g   = idx & 7;
        cp16(sb + (uint32_t)(row * LDA + g * 4) * 4, ws + (size_t)row * CIN + g * 4);
    }
}

} // namespace sfc

using namespace sfc;

__global__ void __launch_bounds__(THREADS, 1)
special_fc_mma_kernel(const float* __restrict__ x,
                      const float* __restrict__ W,
                      const float* __restrict__ bias,
                      float* __restrict__ out) {
    extern __shared__ float smem[];
    const uint32_t smem_base = smem_u32(smem);
    const int tid  = threadIdx.x;
    const int warp = tid >> 5;
    const int lane = tid & 31;
    const int rg   = lane >> 2;   // groupID (0..7)
    const int tg   = lane & 3;    // thread-in-group (0..3)

    // Block decomposition: 4 consecutive CTAs share the x tile (n varies
    // fastest), 256 consecutive CTAs share W[b].
    const int b   = blockIdx.x >> 8;
    const int rem = blockIdx.x & 255;
    const int m0  = (rem >> 2) * BM;
    const int n0  = (rem & 3) * BN;

    // Warp tile: 64 (m) x 32 (n).  wm in {0,1}, wn in {0..3}.
    const int wm = warp >> 2;
    const int wn = warp & 3;

    float acc[4][4][4];           // [mt][nt][c0..c3]
#pragma unroll
    for (int mt = 0; mt < 4; mt++)
#pragma unroll
        for (int nt = 0; nt < 4; nt++)
#pragma unroll
            for (int j = 0; j < 4; j++)
                acc[mt][nt][j] = 0.0f;

    // ---- prologue: 3 chunks in flight ----
#pragma unroll
    for (int s = 0; s < NSTAGE - 1; s++) {
        load_chunk(x, W, smem_base, s, b, m0, n0, s * BK, tid);
        asm volatile("cp.async.commit_group;" ::: "memory");
    }

    // ---- main loop over K chunks ----
#pragma unroll 1
    for (int c = 0; c < CHUNKS; ++c) {
        asm volatile("cp.async.wait_group %0;" :: "n"(NSTAGE - 2) : "memory");
        __syncthreads();

        // refill the stage freed by chunk c-1 (computed last iteration)
        if (c + NSTAGE - 1 < CHUNKS) {
            load_chunk(x, W, smem_base, (c + NSTAGE - 1) & (NSTAGE - 1),
                       b, m0, n0, (c + NSTAGE - 1) * BK, tid);
        }
        asm volatile("cp.async.commit_group;" ::: "memory");

        const float* As = smem + (size_t)(c & (NSTAGE - 1)) * STAGE_F;
        const float* Bs = As + STAGE_AF;

#pragma unroll
        for (int kk = 0; kk < BK; kk += 8) {
            uint32_t afr[4][4];
#pragma unroll
            for (int mt = 0; mt < 4; mt++) {
                const float* ap = As + (wm * 64 + mt * 16 + rg) * LDA + kk + tg;
                afr[mt][0] = tf32_of(ap[0]);
                afr[mt][1] = tf32_of(ap[8 * LDA]);
                afr[mt][2] = tf32_of(ap[4]);
                afr[mt][3] = tf32_of(ap[8 * LDA + 4]);
            }
            uint32_t bfr[4][2];
#pragma unroll
            for (int nt = 0; nt < 4; nt++) {
                const float* bp = Bs + (wn * 32 + nt * 8 + rg) * LDA + kk + tg;
                bfr[nt][0] = tf32_of(bp[0]);
                bfr[nt][1] = tf32_of(bp[4]);
            }
#pragma unroll
            for (int mt = 0; mt < 4; mt++)
#pragma unroll
                for (int nt = 0; nt < 4; nt++)
                    mma8(acc[mt][nt], afr[mt], bfr[nt]);
        }
        __syncthreads();
    }

    // ---- epilogue: bias add + float2 stores ----
    float2 bv[4];
#pragma unroll
    for (int nt = 0; nt < 4; nt++) {
        const int col = n0 + wn * 32 + nt * 8 + 2 * tg;
        bv[nt] = *reinterpret_cast<const float2*>(bias + b * COUT + col);
    }

#pragma unroll
    for (int mt = 0; mt < 4; mt++) {
        const int rbase = m0 + wm * 64 + mt * 16 + rg;
#pragma unroll
        for (int half = 0; half < 2; half++) {
            float* po = out + ((size_t)b * NSEQ + rbase + half * 8) * COUT;
#pragma unroll
            for (int nt = 0; nt < 4; nt++) {
                const int col = n0 + wn * 32 + nt * 8 + 2 * tg;
                float2 v;
                v.x = acc[mt][nt][half * 2 + 0] + bv[nt].x;
                v.y = acc[mt][nt][half * 2 + 1] + bv[nt].y;
                *reinterpret_cast<float2*>(po + col) = v;
            }
        }
    }
}

extern "C" void kernel_launch(void* const* d_in, const int* in_sizes, int n_in,
                              void* d_out, int out_size) {
    const float* x    = (const float*)d_in[0];
    const float* W    = (const float*)d_in[1];
    const float* bias = (const float*)d_in[2];
    float* out        = (float*)d_out;

    cudaFuncSetAttribute(special_fc_mma_kernel,
                         cudaFuncAttributeMaxDynamicSharedMemorySize, SMEM_TOTAL);
    special_fc_mma_kernel<<<GRID, THREADS, SMEM_TOTAL>>>(x, W, bias, out);
}